// round 2
// baseline (speedup 1.0000x reference)
#include <cuda_runtime.h>
#include <math.h>

// Problem constants: x [B=8, I=32, O=32, D=8, H=14, W=14, kh=3, kw=3] fp32
// out [B, O, D, H, W] fp32
namespace {
constexpr int Bn = 8, In = 32, On = 32, Dn = 8, Hn = 14, Wn = 14, Kn = 9;
constexpr int WK   = Wn * Kn;   // 126 contiguous floats per (b,i,o,d,h)
constexpr int SLAB = Dn * WK;   // 1008 floats = 4032 B per (b,i,o,h) slab
constexpr int NT   = 256;
constexpr int SUBK = 26;        // ceil(0.8 * 32)
}

__device__ __forceinline__ void cp_async8(void* sm, const void* gm) {
    unsigned s = (unsigned)__cvta_generic_to_shared(sm);
    asm volatile("cp.async.ca.shared.global [%0], [%1], 8;\n" :: "r"(s), "l"(gm));
}
__device__ __forceinline__ void cp_commit() {
    asm volatile("cp.async.commit_group;\n");
}
template <int N>
__device__ __forceinline__ void cp_wait() {
    asm volatile("cp.async.wait_group %0;\n" :: "n"(N));
}

// Monotone float -> uint key: a <= b  <=>  fkey(a) <= fkey(b)
__device__ __forceinline__ unsigned fkey(float f) {
    unsigned u = __float_as_uint(f);
    return u ^ (unsigned)(((int)u >> 31) | 0x80000000);
}

__global__ void __launch_bounds__(NT)
caps_route_kernel(const float* __restrict__ x, float* __restrict__ out) {
    const int h = blockIdx.x, o = blockIdx.y, b = blockIdx.z;
    const int tid = threadIdx.x;

    __shared__ __align__(16) float sl[2][SLAB];   // double-buffered input slab
    __shared__ float    sNorm[WK];                 // per-(w,k) norm over D
    __shared__ float    sXavg[In * Dn * Wn];       // [i][d][w] kernel-averaged poses
    __shared__ float    sNI[In * Wn];              // [i][w] norm over D of xavg
    __shared__ float    sV[Dn * Wn];               // consensus v [d][w]
    __shared__ float    sLoss[In * Wn];            // [i][w]
    __shared__ unsigned sThr[Wn];                  // threshold keys per w

    const long strideD = (long)Hn * Wn * Kn;       // 1764
    const long strideO = Dn * strideD;             // 14112
    const long strideI = On * strideO;             // 451584
    const long strideB = In * strideI;             // 14450688
    const float* base = x + (long)b * strideB + (long)o * strideO + (long)h * WK;

    // ---- prefetch slab i=0 ----
    {
        const float* g = base;
        for (int j = tid; j < SLAB / 2; j += NT) {
            int d = j / 63, c = j - d * 63;
            cp_async8(&sl[0][d * WK + 2 * c], g + d * strideD + 2 * c);
        }
        cp_commit();
    }
    if (tid < Wn) sThr[tid] = 0u;

    // ---- Phase 1: per input capsule i, compute kernel-position weighted avg ----
    for (int i = 0; i < In; ++i) {
        const int cur = i & 1;
        if (i + 1 < In) {
            const float* g = base + (long)(i + 1) * strideI;
            float* dst = sl[cur ^ 1];
            for (int j = tid; j < SLAB / 2; j += NT) {
                int d = j / 63, c = j - d * 63;
                cp_async8(&dst[d * WK + 2 * c], g + d * strideD + 2 * c);
            }
            cp_commit();
            cp_wait<1>();   // oldest group (current buffer) complete
        } else {
            cp_wait<0>();
        }
        __syncthreads();

        const float* s = sl[cur];
        // norms over D for each of the 126 (w,k) positions
        for (int wk = tid; wk < WK; wk += NT) {
            float acc = 0.f;
            #pragma unroll
            for (int d = 0; d < Dn; ++d) {
                float v = s[d * WK + wk];
                acc += v * v;
            }
            sNorm[wk] = sqrtf(acc);
        }
        __syncthreads();

        // xavg[d][w] = sum_k n_k * x[d][w][k] / sum_k n_k
        for (int t = tid; t < Dn * Wn; t += NT) {
            int d = t / Wn, w = t - d * Wn;
            float num = 0.f, den = 0.f;
            #pragma unroll
            for (int k = 0; k < Kn; ++k) {
                float nk = sNorm[w * Kn + k];
                num += nk * s[d * WK + w * Kn + k];
                den += nk;
            }
            sXavg[(i * Dn + d) * Wn + w] = num / den;
        }
        __syncthreads();
    }

    // ---- Phase 2: reductions over input capsules (all in SMEM) ----
    // nI[i][w] = || xavg[i,:,w] ||
    for (int p = tid; p < In * Wn; p += NT) {
        int i = p / Wn, w = p - i * Wn;
        float acc = 0.f;
        #pragma unroll
        for (int d = 0; d < Dn; ++d) {
            float v = sXavg[(i * Dn + d) * Wn + w];
            acc += v * v;
        }
        sNI[p] = sqrtf(acc);
    }
    __syncthreads();

    // consensus v[d][w] = sum_i nI * xavg / sum_i nI
    for (int t = tid; t < Dn * Wn; t += NT) {
        int d = t / Wn, w = t - d * Wn;
        float num = 0.f, den = 0.f;
        #pragma unroll 4
        for (int i = 0; i < In; ++i) {
            float n = sNI[i * Wn + w];
            num += n * sXavg[(i * Dn + d) * Wn + w];
            den += n;
        }
        sV[t] = num / den;
    }
    __syncthreads();

    // losses[i][w] = -<v[:, w], xavg[i,:,w]>
    for (int p = tid; p < In * Wn; p += NT) {
        int i = p / Wn, w = p - i * Wn;
        float acc = 0.f;
        #pragma unroll
        for (int d = 0; d < Dn; ++d)
            acc += sV[d * Wn + w] * sXavg[(i * Dn + d) * Wn + w];
        sLoss[p] = -acc;
    }
    __syncthreads();

    // kth-smallest (k = SUBK) with exact tie semantics:
    // thr = max{ v in losses : #(x < v) <= SUBK-1 }  == sorted[SUBK-1]
    for (int p = tid; p < In * Wn; p += NT) {
        int i = p / Wn, w = p - i * Wn;
        float mine = sLoss[i * Wn + w];
        int cnt = 0;
        #pragma unroll 8
        for (int j = 0; j < In; ++j)
            cnt += (sLoss[j * Wn + w] < mine);
        if (cnt <= SUBK - 1)
            atomicMax(&sThr[w], fkey(mine));
    }
    __syncthreads();

    // masked re-average (choose = losses <= thr), write output
    for (int t = tid; t < Dn * Wn; t += NT) {
        int d = t / Wn, w = t - d * Wn;
        const unsigned thr = sThr[w];
        float num = 0.f, den = 0.f;
        #pragma unroll 4
        for (int i = 0; i < In; ++i) {
            if (fkey(sLoss[i * Wn + w]) <= thr) {
                float n = sNI[i * Wn + w];
                num += n * sXavg[(i * Dn + d) * Wn + w];
                den += n;
            }
        }
        out[(((long)b * On + o) * Dn + d) * (Hn * Wn) + h * Wn + w] = num / den;
    }
}

extern "C" void kernel_launch(void* const* d_in, const int* in_sizes, int n_in,
                              void* d_out, int out_size) {
    const float* x = (const float*)d_in[0];
    float* out = (float*)d_out;
    dim3 grid(Hn, On, Bn);   // 14 x 32 x 8 = 3584 CTAs
    caps_route_kernel<<<grid, NT>>>(x, out);
}